// round 14
// baseline (speedup 1.0000x reference)
#include <cuda_runtime.h>

// Problem constants
constexpr int kS = 2048;   // seq len
constexpr int kB = 64;     // batch
constexpr int kE = 512;    // embed
constexpr int kH = 256;    // hidden
constexpr int kG = 1024;   // 4*H

// Scratch for input projections: [2 dirs][S][B][4H] fp32 = 1.07 GB
__device__ float g_gx[2u * 2048u * 64u * 1024u];

// ---------------------------------------------------------------------------
// Helpers
// ---------------------------------------------------------------------------
__device__ __forceinline__ unsigned f2tf(float x) {
    unsigned r;
    asm("cvt.rna.tf32.f32 %0, %1;" : "=r"(r) : "f"(x));
    return r;
}

__device__ __forceinline__ void mma_tf32(float* c, const unsigned* a, const unsigned* b) {
    asm volatile(
        "mma.sync.aligned.m16n8k8.row.col.f32.tf32.tf32.f32 "
        "{%0,%1,%2,%3},{%4,%5,%6,%7},{%8,%9},{%0,%1,%2,%3};"
        : "+f"(c[0]), "+f"(c[1]), "+f"(c[2]), "+f"(c[3])
        : "r"(a[0]), "r"(a[1]), "r"(a[2]), "r"(a[3]), "r"(b[0]), "r"(b[1]));
}

__device__ __forceinline__ float sigf(float x) { return 1.f / (1.f + __expf(-x)); }
__device__ __forceinline__ float tanhf_(float x) { return 1.f - 2.f / (__expf(2.f * x) + 1.f); }

// ---------------------------------------------------------------------------
// Kernel 1: input projection GEMM (tf32 mma.sync), per direction (unchanged)
// ---------------------------------------------------------------------------
__global__ void __launch_bounds__(128) gemm_in(
    const float* __restrict__ X,
    const float* __restrict__ Wf, const float* __restrict__ bif, const float* __restrict__ bhf,
    const float* __restrict__ Wb, const float* __restrict__ bib, const float* __restrict__ bhb)
{
    __shared__ unsigned As[64 * 20];
    __shared__ unsigned Bs[64 * 20];

    const int ntile = blockIdx.x;       // 0..15
    const int s     = blockIdx.y;       // 0..2047
    const int d     = blockIdx.z;       // 0..1
    const float* W  = d == 0 ? Wf : Wb;
    const float* bi = d == 0 ? bif : bib;
    const float* bh = d == 0 ? bhf : bhb;
    const int n0 = ntile * 64;

    const int tid  = threadIdx.x;
    const int lane = tid & 31;
    const int warp = tid >> 5;
    const int g  = lane >> 2;
    const int t4 = lane & 3;
    const int wm = (warp >> 1) * 32;
    const int wn = (warp & 1) * 32;

    float acc[2][4][4];
#pragma unroll
    for (int mi = 0; mi < 2; mi++)
#pragma unroll
        for (int ni = 0; ni < 4; ni++)
#pragma unroll
            for (int q = 0; q < 4; q++) acc[mi][ni][q] = 0.f;

    const int lr = tid >> 2;
    const int lc = (tid & 3) * 4;

    for (int k0 = 0; k0 < kE; k0 += 16) {
        __syncthreads();
#pragma unroll
        for (int rr = 0; rr < 2; rr++) {
            const int row = lr + rr * 32;
            float4 va = *(const float4*)(X + ((size_t)row * kS + s) * kE + k0 + lc);
            unsigned* da = &As[row * 20 + lc];
            da[0] = f2tf(va.x); da[1] = f2tf(va.y); da[2] = f2tf(va.z); da[3] = f2tf(va.w);
            float4 vb = *(const float4*)(W + (size_t)(n0 + row) * kE + k0 + lc);
            unsigned* db = &Bs[row * 20 + lc];
            db[0] = f2tf(vb.x); db[1] = f2tf(vb.y); db[2] = f2tf(vb.z); db[3] = f2tf(vb.w);
        }
        __syncthreads();

#pragma unroll
        for (int kk = 0; kk < 2; kk++) {
            const int kb = kk * 8;
            unsigned a[2][4], b[4][2];
#pragma unroll
            for (int mi = 0; mi < 2; mi++) {
                const int ar = wm + mi * 16;
                a[mi][0] = As[(ar + g) * 20 + kb + t4];
                a[mi][1] = As[(ar + g + 8) * 20 + kb + t4];
                a[mi][2] = As[(ar + g) * 20 + kb + t4 + 4];
                a[mi][3] = As[(ar + g + 8) * 20 + kb + t4 + 4];
            }
#pragma unroll
            for (int ni = 0; ni < 4; ni++) {
                const int bc = wn + ni * 8;
                b[ni][0] = Bs[(bc + g) * 20 + kb + t4];
                b[ni][1] = Bs[(bc + g) * 20 + kb + t4 + 4];
            }
#pragma unroll
            for (int mi = 0; mi < 2; mi++)
#pragma unroll
                for (int ni = 0; ni < 4; ni++)
                    mma_tf32(acc[mi][ni], a[mi], b[ni]);
        }
    }

    const size_t rbase = ((size_t)d * kS + s) * kB;
#pragma unroll
    for (int ni = 0; ni < 4; ni++) {
        const int col = n0 + wn + ni * 8 + t4 * 2;
        const float bs0 = bi[col] + bh[col];
        const float bs1 = bi[col + 1] + bh[col + 1];
#pragma unroll
        for (int mi = 0; mi < 2; mi++) {
            const int r0 = wm + mi * 16 + g;
            float2 v;
            v.x = acc[mi][ni][0] + bs0; v.y = acc[mi][ni][1] + bs1;
            *(float2*)&g_gx[(rbase + r0) * kG + col] = v;
            v.x = acc[mi][ni][2] + bs0; v.y = acc[mi][ni][3] + bs1;
            *(float2*)&g_gx[(rbase + r0 + 8) * kG + col] = v;
        }
    }
}

// ---------------------------------------------------------------------------
// Kernel 2: recurrence on tensor cores, WARP-AUTONOMOUS steps.
// 16 clusters of 8 CTAs, 256 thr/CTA. CTA rank c owns units [c*32, c*32+32).
// Warp w owns gate rows 16w..16w+16 = ALL 4 gates of units 4w..4w+3, as
// persistent full-M tf32 A-fragments (128 regs). Per step, entirely within
// the warp: mma (K=256, dual chains) -> 2-round shfl transpose (each thread
// ends with i,f,g,o of one (unit,batch)) -> gate math -> shfl-pack float4
// per batch -> 7 remote DSMEM st.v4 (rotated peers) -> __syncwarp ->
// lanes 0..7 release-arrive at rank=lane.
// TWO phase-alternating mbarriers (count 64 = 8 warps x 8 CTAs), indexed by
// step&1, parity (step>>1)&1: prevents the cross-phase arrival race that a
// single parity mbarrier has when arrivers don't wait on the remote barrier
// (an s+1 arrival can only hit a barrier whose s-1 phase provably completed).
// NO __syncthreads, NO cluster fence, NO gp SMEM exchange in the loop.
// ---------------------------------------------------------------------------
constexpr int HB_STR = 260;   // h row stride: conflict-free b-frag LDS

__global__ void __launch_bounds__(256, 1) lstm_rec(
    const float* __restrict__ whf, const float* __restrict__ whb,
    const float* __restrict__ h0f, const float* __restrict__ c0f,
    const float* __restrict__ h0b, const float* __restrict__ c0b,
    float* __restrict__ out)
{
    __shared__ alignas(16) float hb[2][8][HB_STR];   // double-buffered h
    __shared__ alignas(8) unsigned long long mbar[2];

    unsigned rank;
    asm("mov.u32 %0, %%cluster_ctarank;" : "=r"(rank));
    unsigned hb_base;
    asm("{ .reg .u64 t; cvta.to.shared.u64 t, %1; cvt.u32.u64 %0, t; }"
        : "=r"(hb_base) : "l"(&hb[0][0][0]));
    unsigned mb_base;
    asm("{ .reg .u64 t; cvta.to.shared.u64 t, %1; cvt.u32.u64 %0, t; }"
        : "=r"(mb_base) : "l"(&mbar[0]));

    const int cid = blockIdx.x >> 3;   // cluster 0..15
    const int dir = cid >> 3;          // 0 fwd, 1 bwd
    const int bg  = cid & 7;
    const int gb0 = bg * 8;
    const int tid = threadIdx.x;
    const int w    = tid >> 5;         // warp 0..7
    const int lane = tid & 31;
    const int g    = lane >> 2;        // fragment group 0..7
    const int t4   = lane & 3;         // thread-in-group
    const int bit2 = (lane >> 2) & 1;
    const int bit3 = (lane >> 3) & 1;
    const int bit4 = (lane >> 4) & 1;

    // Gate-phase ownership: one (unit, batch) per thread
    const int u_idx = 2 * bit3 + bit4;              // 0..3
    const int u     = 4 * w + u_idx;                // CTA-local unit 0..31
    const int gb    = ((lane & 3) << 1) | bit2;     // batch-in-group 0..7

    const float* whh = dir == 0 ? whf : whb;
    const float* h0  = dir == 0 ? h0f : h0b;
    const float* c0  = dir == 0 ? c0f : c0b;

    // mbarriers: 64 arrivals per phase (8 warps x 8 CTAs, one lane each)
    if (tid == 0) {
        asm volatile("mbarrier.init.shared.b64 [%0], %1;" :: "r"(mb_base), "r"(64u) : "memory");
        asm volatile("mbarrier.init.shared.b64 [%0], %1;" :: "r"(mb_base + 8), "r"(64u) : "memory");
    }

    // Persistent FULL-M A-fragments: rows r_lo = 16w+g, r_hi = r_lo+8
    const int r_lo = 16 * w + g;
    const int r_hi = r_lo + 8;
    const int wr_lo = (r_lo & 3) * 256 + (int)rank * 32 + (r_lo >> 2);
    const int wr_hi = (r_hi & 3) * 256 + (int)rank * 32 + (r_hi >> 2);
    unsigned a0[32], a1[32], a2[32], a3[32];
#pragma unroll
    for (int kc = 0; kc < 32; kc++) {
        a0[kc] = f2tf(whh[(size_t)wr_lo * kH + kc * 8 + t4]);
        a1[kc] = f2tf(whh[(size_t)wr_hi * kH + kc * 8 + t4]);
        a2[kc] = f2tf(whh[(size_t)wr_lo * kH + kc * 8 + t4 + 4]);
        a3[kc] = f2tf(whh[(size_t)wr_hi * kH + kc * 8 + t4 + 4]);
    }

    // Load h0 into buffer 0 (tf32-rounded, consistent with mainloop h)
    for (int idx = tid; idx < 8 * 64; idx += 256) {
        const int b = idx >> 6, k4 = (idx & 63) * 4;
        float4 v = *(const float4*)(h0 + (size_t)(gb0 + b) * kH + k4);
        float4 o4;
        o4.x = __uint_as_float(f2tf(v.x)); o4.y = __uint_as_float(f2tf(v.y));
        o4.z = __uint_as_float(f2tf(v.z)); o4.w = __uint_as_float(f2tf(v.w));
        *(float4*)&hb[0][b][k4] = o4;
    }

    float cst = c0[(size_t)(gb0 + gb) * kH + (int)rank * 32 + u];
    const size_t gx_addr0 = ((size_t)dir * kS * kB + (gb0 + gb)) * kG
                            + (size_t)rank * 32 + u;

    __syncthreads();
    // One-time cluster barrier: peers' mbarrier init + h0 visible before use
    asm volatile("barrier.cluster.arrive.aligned;" ::: "memory");
    asm volatile("barrier.cluster.wait.aligned;" ::: "memory");

    // Preload gx for step 0
    float gx0, gx1, gx2, gx3;
    {
        const int t0 = (dir == 0) ? 0 : (kS - 1);
        const size_t a = gx_addr0 + (size_t)t0 * (kB * kG);
        gx0 = g_gx[a]; gx1 = g_gx[a + 256]; gx2 = g_gx[a + 512]; gx3 = g_gx[a + 768];
    }

    int p = 0;
    for (int step = 0; step < kS; step++) {
        const int t = (dir == 0) ? step : (kS - 1 - step);

        // Prefetch NEXT step's gx (hidden under the mma loop)
        float gn0 = 0.f, gn1 = 0.f, gn2 = 0.f, gn3 = 0.f;
        if (step + 1 < kS) {
            const int tn = (dir == 0) ? (step + 1) : (kS - 2 - step);
            const size_t a = gx_addr0 + (size_t)tn * (kB * kG);
            gn0 = g_gx[a]; gn1 = g_gx[a + 256]; gn2 = g_gx[a + 512]; gn3 = g_gx[a + 768];
        }

        // Tensor mainloop over K=256: two independent accumulation chains
        float cE[4] = {0.f, 0.f, 0.f, 0.f};
        float cO[4] = {0.f, 0.f, 0.f, 0.f};
        const float* hcur = &hb[p][0][0];
        const int hoff = g * HB_STR + t4;
#pragma unroll
        for (int kc = 0; kc < 32; kc += 2) {
            {
                const unsigned b0 = __float_as_uint(hcur[hoff + kc * 8]);
                const unsigned b1 = __float_as_uint(hcur[hoff + kc * 8 + 4]);
                const unsigned af[4] = {a0[kc], a1[kc], a2[kc], a3[kc]};
                const unsigned bf[2] = {b0, b1};
                mma_tf32(cE, af, bf);
            }
            {
                const unsigned b0 = __float_as_uint(hcur[hoff + (kc + 1) * 8]);
                const unsigned b1 = __float_as_uint(hcur[hoff + (kc + 1) * 8 + 4]);
                const unsigned af[4] = {a0[kc + 1], a1[kc + 1], a2[kc + 1], a3[kc + 1]};
                const unsigned bf[2] = {b0, b1};
                mma_tf32(cO, af, bf);
            }
        }

        // Thread (g,t4) holds: v0=(row r_lo, b=2t4), v1=(r_lo, 2t4+1),
        //                      v2=(r_hi, 2t4),     v3=(r_hi, 2t4+1)
        const float v0 = cE[0] + cO[0];
        const float v1 = cE[1] + cO[1];
        const float v2 = cE[2] + cO[2];
        const float v3 = cE[3] + cO[3];

        // Round 1 (xor 4): keep batch-parity == bit2, trade for gate-bit0
        const float keepA = bit2 ? v1 : v0;
        const float sendA = bit2 ? v0 : v1;
        const float keepB = bit2 ? v3 : v2;
        const float sendB = bit2 ? v2 : v3;
        const float gotA = __shfl_xor_sync(0xffffffffu, sendA, 4);
        const float gotB = __shfl_xor_sync(0xffffffffu, sendB, 4);
        const float a_g0 = bit2 ? gotA : keepA;   // (u_hi=0, gate bit0 = 0)
        const float a_g1 = bit2 ? keepA : gotA;   // (u_hi=0, gate bit0 = 1)
        const float b_g0 = bit2 ? gotB : keepB;   // (u_hi=1, gate bit0 = 0)
        const float b_g1 = bit2 ? keepB : gotB;

        // Round 2 (xor 8): keep unit_hi == bit3, trade for gate-bit1
        const float keepX = bit3 ? b_g0 : a_g0;
        const float sendX = bit3 ? a_g0 : b_g0;
        const float keepY = bit3 ? b_g1 : a_g1;
        const float sendY = bit3 ? a_g1 : b_g1;
        const float gotX = __shfl_xor_sync(0xffffffffu, sendX, 8);
        const float gotY = __shfl_xor_sync(0xffffffffu, sendY, 8);
        const float pi = bit3 ? gotX : keepX;   // gate 0 (i)
        const float pf = bit3 ? gotY : keepY;   // gate 1 (f)
        const float pg = bit3 ? keepX : gotX;   // gate 2 (g)
        const float po = bit3 ? keepY : gotY;   // gate 3 (o)

        // Gate math for (unit u, batch gb)
        const float gi = pi + gx0;
        const float gf = pf + gx1;
        const float gg = pg + gx2;
        const float go = po + gx3;
        cst = sigf(gf) * cst + sigf(gi) * tanhf_(gg);
        const float hnew = sigf(go) * tanhf_(cst);
        const float hr = __uint_as_float(f2tf(hnew));   // rounded for recurrence

        hb[p ^ 1][gb][(int)rank * 32 + u] = hr;
        out[(((size_t)(gb0 + gb)) * kS + t) * 512
            + dir * kH + (int)rank * 32 + u] = hnew;

        if (step + 1 < kS) {
            // Pack units 4w..4w+3 of this thread's batch into a float4.
            // Lanes 0..7 (bits3,4 = 0) end holding their batch's full pack.
            const float p1 = __shfl_xor_sync(0xffffffffu, hr, 16);  // u_idx 1
            const float p2 = __shfl_xor_sync(0xffffffffu, hr, 8);   // u_idx 2
            const float p3 = __shfl_xor_sync(0xffffffffu, hr, 24);  // u_idx 3
            if (lane < 8) {
                const unsigned loff = hb_base +
                    (unsigned)((((p ^ 1) * 8 + gb) * HB_STR)
                               + (int)rank * 32 + 4 * w) * 4u;
#pragma unroll
                for (int j = 0; j < 7; j++) {
                    const unsigned tr = (rank + 1u + (unsigned)((lane + j) % 7)) & 7u;
                    unsigned raddr;
                    asm("mapa.shared::cluster.u32 %0, %1, %2;"
                        : "=r"(raddr) : "r"(loff), "r"(tr));
                    asm volatile("st.shared::cluster.v4.f32 [%0], {%1,%2,%3,%4};"
                                 :: "r"(raddr), "f"(hr), "f"(p1), "f"(p2), "f"(p3));
                }
            }
            __syncwarp();   // HB: all lanes' stores precede the arrivals below
            const unsigned mb_q = mb_base + (unsigned)((step & 1) * 8);
            if (lane < 8) {
                unsigned raddr;
                asm("mapa.shared::cluster.u32 %0, %1, %2;"
                    : "=r"(raddr) : "r"(mb_q), "r"((unsigned)lane));
                asm volatile("mbarrier.arrive.release.cluster.shared::cluster.b64 _, [%0];"
                             :: "r"(raddr) : "memory");
            }
            // Wait for all 64 warp-arrivals of this step (alternating mbar,
            // parity flips every second use of each barrier).
            const unsigned par = (unsigned)((step >> 1) & 1);
            unsigned done = 0;
            while (!done) {
                asm volatile(
                    "{\n\t.reg .pred p;\n\t"
                    "mbarrier.try_wait.parity.acquire.cluster.shared::cta.b64 p, [%1], %2;\n\t"
                    "selp.b32 %0, 1, 0, p;\n\t}"
                    : "=r"(done) : "r"(mb_q), "r"(par) : "memory");
            }
        }

        gx0 = gn0; gx1 = gn1; gx2 = gn2; gx3 = gn3;
        p ^= 1;
    }

    // Keep SMEM alive until all peers are past their last remote stores
    asm volatile("barrier.cluster.arrive.aligned;" ::: "memory");
    asm volatile("barrier.cluster.wait.aligned;" ::: "memory");
}

// ---------------------------------------------------------------------------
// Launch
// ---------------------------------------------------------------------------
extern "C" void kernel_launch(void* const* d_in, const int* in_sizes, int n_in,
                              void* d_out, int out_size)
{
    const float* X   = (const float*)d_in[0];
    const float* Wf  = (const float*)d_in[1];
    const float* Whf = (const float*)d_in[2];
    const float* bif = (const float*)d_in[3];
    const float* bhf = (const float*)d_in[4];
    const float* Wb  = (const float*)d_in[5];
    const float* Whb = (const float*)d_in[6];
    const float* bib = (const float*)d_in[7];
    const float* bhb = (const float*)d_in[8];
    const float* h0f = (const float*)d_in[9];
    const float* c0f = (const float*)d_in[10];
    const float* h0b = (const float*)d_in[11];
    const float* c0b = (const float*)d_in[12];
    float* out = (float*)d_out;

    dim3 g1(16, 2048, 2);
    gemm_in<<<g1, 128>>>(X, Wf, bif, bhf, Wb, bib, bhb);

    cudaLaunchConfig_t cfg = {};
    cfg.gridDim = dim3(128, 1, 1);
    cfg.blockDim = dim3(256, 1, 1);
    cfg.dynamicSmemBytes = 0;
    cfg.stream = 0;
    cudaLaunchAttribute attr[1];
    attr[0].id = cudaLaunchAttributeClusterDimension;
    attr[0].val.clusterDim.x = 8;
    attr[0].val.clusterDim.y = 1;
    attr[0].val.clusterDim.z = 1;
    cfg.attrs = attr;
    cfg.numAttrs = 1;
    cudaLaunchKernelEx(&cfg, lstm_rec, Whf, Whb, h0f, c0f, h0b, c0b, out);
}

// round 15
// speedup vs baseline: 1.0122x; 1.0122x over previous
#include <cuda_runtime.h>

// Problem constants
constexpr int kS = 2048;   // seq len
constexpr int kB = 64;     // batch
constexpr int kE = 512;    // embed
constexpr int kH = 256;    // hidden
constexpr int kG = 1024;   // 4*H

// Scratch for input projections: [2 dirs][S][B][4H] fp32 = 1.07 GB
__device__ float g_gx[2u * 2048u * 64u * 1024u];

// ---------------------------------------------------------------------------
// Helpers
// ---------------------------------------------------------------------------
__device__ __forceinline__ unsigned f2tf(float x) {
    unsigned r;
    asm("cvt.rna.tf32.f32 %0, %1;" : "=r"(r) : "f"(x));
    return r;
}

__device__ __forceinline__ void mma_tf32(float* c, const unsigned* a, const unsigned* b) {
    asm volatile(
        "mma.sync.aligned.m16n8k8.row.col.f32.tf32.tf32.f32 "
        "{%0,%1,%2,%3},{%4,%5,%6,%7},{%8,%9},{%0,%1,%2,%3};"
        : "+f"(c[0]), "+f"(c[1]), "+f"(c[2]), "+f"(c[3])
        : "r"(a[0]), "r"(a[1]), "r"(a[2]), "r"(a[3]), "r"(b[0]), "r"(b[1]));
}

__device__ __forceinline__ float sigf(float x) { return 1.f / (1.f + __expf(-x)); }
__device__ __forceinline__ float tanhf_(float x) { return 1.f - 2.f / (__expf(2.f * x) + 1.f); }

// ---------------------------------------------------------------------------
// Kernel 1: input projection GEMM (tf32 mma.sync), per direction (unchanged)
// ---------------------------------------------------------------------------
__global__ void __launch_bounds__(128) gemm_in(
    const float* __restrict__ X,
    const float* __restrict__ Wf, const float* __restrict__ bif, const float* __restrict__ bhf,
    const float* __restrict__ Wb, const float* __restrict__ bib, const float* __restrict__ bhb)
{
    __shared__ unsigned As[64 * 20];
    __shared__ unsigned Bs[64 * 20];

    const int ntile = blockIdx.x;       // 0..15
    const int s     = blockIdx.y;       // 0..2047
    const int d     = blockIdx.z;       // 0..1
    const float* W  = d == 0 ? Wf : Wb;
    const float* bi = d == 0 ? bif : bib;
    const float* bh = d == 0 ? bhf : bhb;
    const int n0 = ntile * 64;

    const int tid  = threadIdx.x;
    const int lane = tid & 31;
    const int warp = tid >> 5;
    const int g  = lane >> 2;
    const int t4 = lane & 3;
    const int wm = (warp >> 1) * 32;
    const int wn = (warp & 1) * 32;

    float acc[2][4][4];
#pragma unroll
    for (int mi = 0; mi < 2; mi++)
#pragma unroll
        for (int ni = 0; ni < 4; ni++)
#pragma unroll
            for (int q = 0; q < 4; q++) acc[mi][ni][q] = 0.f;

    const int lr = tid >> 2;
    const int lc = (tid & 3) * 4;

    for (int k0 = 0; k0 < kE; k0 += 16) {
        __syncthreads();
#pragma unroll
        for (int rr = 0; rr < 2; rr++) {
            const int row = lr + rr * 32;
            float4 va = *(const float4*)(X + ((size_t)row * kS + s) * kE + k0 + lc);
            unsigned* da = &As[row * 20 + lc];
            da[0] = f2tf(va.x); da[1] = f2tf(va.y); da[2] = f2tf(va.z); da[3] = f2tf(va.w);
            float4 vb = *(const float4*)(W + (size_t)(n0 + row) * kE + k0 + lc);
            unsigned* db = &Bs[row * 20 + lc];
            db[0] = f2tf(vb.x); db[1] = f2tf(vb.y); db[2] = f2tf(vb.z); db[3] = f2tf(vb.w);
        }
        __syncthreads();

#pragma unroll
        for (int kk = 0; kk < 2; kk++) {
            const int kb = kk * 8;
            unsigned a[2][4], b[4][2];
#pragma unroll
            for (int mi = 0; mi < 2; mi++) {
                const int ar = wm + mi * 16;
                a[mi][0] = As[(ar + g) * 20 + kb + t4];
                a[mi][1] = As[(ar + g + 8) * 20 + kb + t4];
                a[mi][2] = As[(ar + g) * 20 + kb + t4 + 4];
                a[mi][3] = As[(ar + g + 8) * 20 + kb + t4 + 4];
            }
#pragma unroll
            for (int ni = 0; ni < 4; ni++) {
                const int bc = wn + ni * 8;
                b[ni][0] = Bs[(bc + g) * 20 + kb + t4];
                b[ni][1] = Bs[(bc + g) * 20 + kb + t4 + 4];
            }
#pragma unroll
            for (int mi = 0; mi < 2; mi++)
#pragma unroll
                for (int ni = 0; ni < 4; ni++)
                    mma_tf32(acc[mi][ni], a[mi], b[ni]);
        }
    }

    const size_t rbase = ((size_t)d * kS + s) * kB;
#pragma unroll
    for (int ni = 0; ni < 4; ni++) {
        const int col = n0 + wn + ni * 8 + t4 * 2;
        const float bs0 = bi[col] + bh[col];
        const float bs1 = bi[col + 1] + bh[col + 1];
#pragma unroll
        for (int mi = 0; mi < 2; mi++) {
            const int r0 = wm + mi * 16 + g;
            float2 v;
            v.x = acc[mi][ni][0] + bs0; v.y = acc[mi][ni][1] + bs1;
            *(float2*)&g_gx[(rbase + r0) * kG + col] = v;
            v.x = acc[mi][ni][2] + bs0; v.y = acc[mi][ni][3] + bs1;
            *(float2*)&g_gx[(rbase + r0 + 8) * kG + col] = v;
        }
    }
}

// ---------------------------------------------------------------------------
// Kernel 2: recurrence on tensor cores. 16 clusters of 8 CTAs, 256 thr/CTA.
// Compute is warp-autonomous (R14): warp w owns all 4 gates of units
// 4w..4w+3 as persistent full-M tf32 A-fragments; per step: mma (K=256,
// dual chains) -> 2-round shfl transpose -> gate math -> shfl-pack ->
// 7-peer DSMEM st.v4. NO gp SMEM exchange.
// Handshake is CTA-aggregated (R10): ONE __syncthreads, then tid<8 send a
// single release-arrive each to rank=tid => only 8 arrivals per mbarrier
// per step (64 arrivals serialized ~32cyc each at the target was R14's
// regression). Dual phase-alternating mbarriers (count 8), parity
// (step>>1)&1; arrivals aggregated behind syncthreads make the phase
// hand-off provably race-free. try_wait uses the HW-sleep hint.
// ---------------------------------------------------------------------------
constexpr int HB_STR = 260;   // h row stride: conflict-free b-frag LDS

__global__ void __launch_bounds__(256, 1) lstm_rec(
    const float* __restrict__ whf, const float* __restrict__ whb,
    const float* __restrict__ h0f, const float* __restrict__ c0f,
    const float* __restrict__ h0b, const float* __restrict__ c0b,
    float* __restrict__ out)
{
    __shared__ alignas(16) float hb[2][8][HB_STR];   // double-buffered h
    __shared__ alignas(8) unsigned long long mbar[2];

    unsigned rank;
    asm("mov.u32 %0, %%cluster_ctarank;" : "=r"(rank));
    unsigned hb_base;
    asm("{ .reg .u64 t; cvta.to.shared.u64 t, %1; cvt.u32.u64 %0, t; }"
        : "=r"(hb_base) : "l"(&hb[0][0][0]));
    unsigned mb_base;
    asm("{ .reg .u64 t; cvta.to.shared.u64 t, %1; cvt.u32.u64 %0, t; }"
        : "=r"(mb_base) : "l"(&mbar[0]));

    const int cid = blockIdx.x >> 3;   // cluster 0..15
    const int dir = cid >> 3;          // 0 fwd, 1 bwd
    const int bg  = cid & 7;
    const int gb0 = bg * 8;
    const int tid = threadIdx.x;
    const int w    = tid >> 5;         // warp 0..7
    const int lane = tid & 31;
    const int g    = lane >> 2;        // fragment group 0..7
    const int t4   = lane & 3;         // thread-in-group
    const int bit2 = (lane >> 2) & 1;
    const int bit3 = (lane >> 3) & 1;
    const int bit4 = (lane >> 4) & 1;

    // Gate-phase ownership: one (unit, batch) per thread
    const int u_idx = 2 * bit3 + bit4;              // 0..3
    const int u     = 4 * w + u_idx;                // CTA-local unit 0..31
    const int gb    = ((lane & 3) << 1) | bit2;     // batch-in-group 0..7

    const float* whh = dir == 0 ? whf : whb;
    const float* h0  = dir == 0 ? h0f : h0b;
    const float* c0  = dir == 0 ? c0f : c0b;

    // mbarriers: 8 arrivals per phase (one per cluster CTA)
    if (tid == 0) {
        asm volatile("mbarrier.init.shared.b64 [%0], %1;" :: "r"(mb_base), "r"(8u) : "memory");
        asm volatile("mbarrier.init.shared.b64 [%0], %1;" :: "r"(mb_base + 8), "r"(8u) : "memory");
    }

    // Persistent FULL-M A-fragments: rows r_lo = 16w+g, r_hi = r_lo+8
    const int r_lo = 16 * w + g;
    const int r_hi = r_lo + 8;
    const int wr_lo = (r_lo & 3) * 256 + (int)rank * 32 + (r_lo >> 2);
    const int wr_hi = (r_hi & 3) * 256 + (int)rank * 32 + (r_hi >> 2);
    unsigned a0[32], a1[32], a2[32], a3[32];
#pragma unroll
    for (int kc = 0; kc < 32; kc++) {
        a0[kc] = f2tf(whh[(size_t)wr_lo * kH + kc * 8 + t4]);
        a1[kc] = f2tf(whh[(size_t)wr_hi * kH + kc * 8 + t4]);
        a2[kc] = f2tf(whh[(size_t)wr_lo * kH + kc * 8 + t4 + 4]);
        a3[kc] = f2tf(whh[(size_t)wr_hi * kH + kc * 8 + t4 + 4]);
    }

    // Load h0 into buffer 0 (tf32-rounded, consistent with mainloop h)
    for (int idx = tid; idx < 8 * 64; idx += 256) {
        const int b = idx >> 6, k4 = (idx & 63) * 4;
        float4 v = *(const float4*)(h0 + (size_t)(gb0 + b) * kH + k4);
        float4 o4;
        o4.x = __uint_as_float(f2tf(v.x)); o4.y = __uint_as_float(f2tf(v.y));
        o4.z = __uint_as_float(f2tf(v.z)); o4.w = __uint_as_float(f2tf(v.w));
        *(float4*)&hb[0][b][k4] = o4;
    }

    float cst = c0[(size_t)(gb0 + gb) * kH + (int)rank * 32 + u];
    const size_t gx_addr0 = ((size_t)dir * kS * kB + (gb0 + gb)) * kG
                            + (size_t)rank * 32 + u;

    __syncthreads();
    // One-time cluster barrier: peers' mbarrier init + h0 visible before use
    asm volatile("barrier.cluster.arrive.aligned;" ::: "memory");
    asm volatile("barrier.cluster.wait.aligned;" ::: "memory");

    // Preload gx for step 0
    float gx0, gx1, gx2, gx3;
    {
        const int t0 = (dir == 0) ? 0 : (kS - 1);
        const size_t a = gx_addr0 + (size_t)t0 * (kB * kG);
        gx0 = g_gx[a]; gx1 = g_gx[a + 256]; gx2 = g_gx[a + 512]; gx3 = g_gx[a + 768];
    }

    int p = 0;
    for (int step = 0; step < kS; step++) {
        const int t = (dir == 0) ? step : (kS - 1 - step);

        // Prefetch NEXT step's gx (hidden under the mma loop)
        float gn0 = 0.f, gn1 = 0.f, gn2 = 0.f, gn3 = 0.f;
        if (step + 1 < kS) {
            const int tn = (dir == 0) ? (step + 1) : (kS - 2 - step);
            const size_t a = gx_addr0 + (size_t)tn * (kB * kG);
            gn0 = g_gx[a]; gn1 = g_gx[a + 256]; gn2 = g_gx[a + 512]; gn3 = g_gx[a + 768];
        }

        // Tensor mainloop over K=256: two independent accumulation chains
        float cE[4] = {0.f, 0.f, 0.f, 0.f};
        float cO[4] = {0.f, 0.f, 0.f, 0.f};
        const float* hcur = &hb[p][0][0];
        const int hoff = g * HB_STR + t4;
#pragma unroll
        for (int kc = 0; kc < 32; kc += 2) {
            {
                const unsigned b0 = __float_as_uint(hcur[hoff + kc * 8]);
                const unsigned b1 = __float_as_uint(hcur[hoff + kc * 8 + 4]);
                const unsigned af[4] = {a0[kc], a1[kc], a2[kc], a3[kc]};
                const unsigned bf[2] = {b0, b1};
                mma_tf32(cE, af, bf);
            }
            {
                const unsigned b0 = __float_as_uint(hcur[hoff + (kc + 1) * 8]);
                const unsigned b1 = __float_as_uint(hcur[hoff + (kc + 1) * 8 + 4]);
                const unsigned af[4] = {a0[kc + 1], a1[kc + 1], a2[kc + 1], a3[kc + 1]};
                const unsigned bf[2] = {b0, b1};
                mma_tf32(cO, af, bf);
            }
        }

        // Thread (g,t4) holds: v0=(row r_lo, b=2t4), v1=(r_lo, 2t4+1),
        //                      v2=(r_hi, 2t4),     v3=(r_hi, 2t4+1)
        const float v0 = cE[0] + cO[0];
        const float v1 = cE[1] + cO[1];
        const float v2 = cE[2] + cO[2];
        const float v3 = cE[3] + cO[3];

        // Round 1 (xor 4): keep batch-parity == bit2, trade for gate-bit0
        const float keepA = bit2 ? v1 : v0;
        const float sendA = bit2 ? v0 : v1;
        const float keepB = bit2 ? v3 : v2;
        const float sendB = bit2 ? v2 : v3;
        const float gotA = __shfl_xor_sync(0xffffffffu, sendA, 4);
        const float gotB = __shfl_xor_sync(0xffffffffu, sendB, 4);
        const float a_g0 = bit2 ? gotA : keepA;   // (u_hi=0, gate bit0 = 0)
        const float a_g1 = bit2 ? keepA : gotA;   // (u_hi=0, gate bit0 = 1)
        const float b_g0 = bit2 ? gotB : keepB;   // (u_hi=1, gate bit0 = 0)
        const float b_g1 = bit2 ? keepB : gotB;

        // Round 2 (xor 8): keep unit_hi == bit3, trade for gate-bit1
        const float keepX = bit3 ? b_g0 : a_g0;
        const float sendX = bit3 ? a_g0 : b_g0;
        const float keepY = bit3 ? b_g1 : a_g1;
        const float sendY = bit3 ? a_g1 : b_g1;
        const float gotX = __shfl_xor_sync(0xffffffffu, sendX, 8);
        const float gotY = __shfl_xor_sync(0xffffffffu, sendY, 8);
        const float pi = bit3 ? gotX : keepX;   // gate 0 (i)
        const float pf = bit3 ? gotY : keepY;   // gate 1 (f)
        const float pg = bit3 ? keepX : gotX;   // gate 2 (g)
        const float po = bit3 ? keepY : gotY;   // gate 3 (o)

        // Gate math for (unit u, batch gb)
        const float gi = pi + gx0;
        const float gf = pf + gx1;
        const float gg = pg + gx2;
        const float go = po + gx3;
        cst = sigf(gf) * cst + sigf(gi) * tanhf_(gg);
        const float hnew = sigf(go) * tanhf_(cst);
        const float hr = __uint_as_float(f2tf(hnew));   // rounded for recurrence

        hb[p ^ 1][gb][(int)rank * 32 + u] = hr;
        out[(((size_t)(gb0 + gb)) * kS + t) * 512
            + dir * kH + (int)rank * 32 + u] = hnew;

        if (step + 1 < kS) {
            // Pack units 4w..4w+3 of this thread's batch into a float4.
            // Lanes 0..7 (bits3,4 = 0) end holding their batch's full pack.
            const float p1 = __shfl_xor_sync(0xffffffffu, hr, 16);  // u_idx 1
            const float p2 = __shfl_xor_sync(0xffffffffu, hr, 8);   // u_idx 2
            const float p3 = __shfl_xor_sync(0xffffffffu, hr, 24);  // u_idx 3
            if (lane < 8) {
                const unsigned loff = hb_base +
                    (unsigned)((((p ^ 1) * 8 + gb) * HB_STR)
                               + (int)rank * 32 + 4 * w) * 4u;
#pragma unroll
                for (int j = 0; j < 7; j++) {
                    const unsigned tr = (rank + 1u + (unsigned)((lane + j) % 7)) & 7u;
                    unsigned raddr;
                    asm("mapa.shared::cluster.u32 %0, %1, %2;"
                        : "=r"(raddr) : "r"(loff), "r"(tr));
                    asm volatile("st.shared::cluster.v4.f32 [%0], {%1,%2,%3,%4};"
                                 :: "r"(raddr), "f"(hr), "f"(p1), "f"(p2), "f"(p3));
                }
            }

            // CTA-aggregated handshake: all warps' stores are ordered behind
            // the syncthreads; then 8 threads send ONE arrival each.
            __syncthreads();
            const unsigned mb_q = mb_base + (unsigned)((step & 1) * 8);
            if (tid < 8) {
                asm volatile("fence.acq_rel.cluster;" ::: "memory");
                unsigned raddr;
                asm("mapa.shared::cluster.u32 %0, %1, %2;"
                    : "=r"(raddr) : "r"(mb_q), "r"((unsigned)tid));
                asm volatile("mbarrier.arrive.release.cluster.shared::cluster.b64 _, [%0];"
                             :: "r"(raddr) : "memory");
            }
            // Wait for all 8 CTA-arrivals (alternating mbar; parity flips
            // every second use of each barrier). HW-sleep hint.
            const unsigned par = (unsigned)((step >> 1) & 1);
            unsigned done = 0;
            while (!done) {
                asm volatile(
                    "{\n\t.reg .pred p;\n\t"
                    "mbarrier.try_wait.parity.acquire.cluster.shared::cta.b64 p, [%1], %2, 0x989680;\n\t"
                    "selp.b32 %0, 1, 0, p;\n\t}"
                    : "=r"(done) : "r"(mb_q), "r"(par) : "memory");
            }
        }

        gx0 = gn0; gx1 = gn1; gx2 = gn2; gx3 = gn3;
        p ^= 1;
    }

    // Keep SMEM alive until all peers are past their last remote stores
    asm volatile("barrier.cluster.arrive.aligned;" ::: "memory");
    asm volatile("barrier.cluster.wait.aligned;" ::: "memory");
}

// ---------------------------------------------------------------------------
// Launch
// ---------------------------------------------------------------------------
extern "C" void kernel_launch(void* const* d_in, const int* in_sizes, int n_in,
                              void* d_out, int out_size)
{
    const float* X   = (const float*)d_in[0];
    const float* Wf  = (const float*)d_in[1];
    const float* Whf = (const float*)d_in[2];
    const float* bif = (const float*)d_in[3];
    const float* bhf = (const float*)d_in[4];
    const float* Wb  = (const float*)d_in[5];
    const float* Whb = (const float*)d_in[6];
    const float* bib = (const float*)d_in[7];
    const float* bhb = (const float*)d_in[8];
    const float* h0f = (const float*)d_in[9];
    const float* c0f = (const float*)d_in[10];
    const float* h0b = (const float*)d_in[11];
    const float* c0b = (const float*)d_in[12];
    float* out = (float*)d_out;

    dim3 g1(16, 2048, 2);
    gemm_in<<<g1, 128>>>(X, Wf, bif, bhf, Wb, bib, bhb);

    cudaLaunchConfig_t cfg = {};
    cfg.gridDim = dim3(128, 1, 1);
    cfg.blockDim = dim3(256, 1, 1);
    cfg.dynamicSmemBytes = 0;
    cfg.stream = 0;
    cudaLaunchAttribute attr[1];
    attr[0].id = cudaLaunchAttributeClusterDimension;
    attr[0].val.clusterDim.x = 8;
    attr[0].val.clusterDim.y = 1;
    attr[0].val.clusterDim.z = 1;
    cfg.attrs = attr;
    cfg.numAttrs = 1;
    cudaLaunchKernelEx(&cfg, lstm_rec, Whf, Whb, h0f, c0f, h0b, c0b, out);
}

// round 16
// speedup vs baseline: 1.0157x; 1.0034x over previous
#include <cuda_runtime.h>

// Problem constants
constexpr int kS = 2048;   // seq len
constexpr int kB = 64;     // batch
constexpr int kE = 512;    // embed
constexpr int kH = 256;    // hidden
constexpr int kG = 1024;   // 4*H

// Scratch for input projections: [2 dirs][S][B][4H] fp32 = 1.07 GB
__device__ float g_gx[2u * 2048u * 64u * 1024u];

// ---------------------------------------------------------------------------
// Helpers
// ---------------------------------------------------------------------------
__device__ __forceinline__ unsigned f2tf(float x) {
    unsigned r;
    asm("cvt.rna.tf32.f32 %0, %1;" : "=r"(r) : "f"(x));
    return r;
}

__device__ __forceinline__ void mma_tf32(float* c, const unsigned* a, const unsigned* b) {
    asm volatile(
        "mma.sync.aligned.m16n8k8.row.col.f32.tf32.tf32.f32 "
        "{%0,%1,%2,%3},{%4,%5,%6,%7},{%8,%9},{%0,%1,%2,%3};"
        : "+f"(c[0]), "+f"(c[1]), "+f"(c[2]), "+f"(c[3])
        : "r"(a[0]), "r"(a[1]), "r"(a[2]), "r"(a[3]), "r"(b[0]), "r"(b[1]));
}

__device__ __forceinline__ float sigf(float x) { return 1.f / (1.f + __expf(-x)); }
__device__ __forceinline__ float tanhf_(float x) { return 1.f - 2.f / (__expf(2.f * x) + 1.f); }

// ---------------------------------------------------------------------------
// Kernel 1: input projection GEMM (tf32 mma.sync), per direction (unchanged)
// ---------------------------------------------------------------------------
__global__ void __launch_bounds__(128) gemm_in(
    const float* __restrict__ X,
    const float* __restrict__ Wf, const float* __restrict__ bif, const float* __restrict__ bhf,
    const float* __restrict__ Wb, const float* __restrict__ bib, const float* __restrict__ bhb)
{
    __shared__ unsigned As[64 * 20];
    __shared__ unsigned Bs[64 * 20];

    const int ntile = blockIdx.x;       // 0..15
    const int s     = blockIdx.y;       // 0..2047
    const int d     = blockIdx.z;       // 0..1
    const float* W  = d == 0 ? Wf : Wb;
    const float* bi = d == 0 ? bif : bib;
    const float* bh = d == 0 ? bhf : bhb;
    const int n0 = ntile * 64;

    const int tid  = threadIdx.x;
    const int lane = tid & 31;
    const int warp = tid >> 5;
    const int g  = lane >> 2;
    const int t4 = lane & 3;
    const int wm = (warp >> 1) * 32;
    const int wn = (warp & 1) * 32;

    float acc[2][4][4];
#pragma unroll
    for (int mi = 0; mi < 2; mi++)
#pragma unroll
        for (int ni = 0; ni < 4; ni++)
#pragma unroll
            for (int q = 0; q < 4; q++) acc[mi][ni][q] = 0.f;

    const int lr = tid >> 2;
    const int lc = (tid & 3) * 4;

    for (int k0 = 0; k0 < kE; k0 += 16) {
        __syncthreads();
#pragma unroll
        for (int rr = 0; rr < 2; rr++) {
            const int row = lr + rr * 32;
            float4 va = *(const float4*)(X + ((size_t)row * kS + s) * kE + k0 + lc);
            unsigned* da = &As[row * 20 + lc];
            da[0] = f2tf(va.x); da[1] = f2tf(va.y); da[2] = f2tf(va.z); da[3] = f2tf(va.w);
            float4 vb = *(const float4*)(W + (size_t)(n0 + row) * kE + k0 + lc);
            unsigned* db = &Bs[row * 20 + lc];
            db[0] = f2tf(vb.x); db[1] = f2tf(vb.y); db[2] = f2tf(vb.z); db[3] = f2tf(vb.w);
        }
        __syncthreads();

#pragma unroll
        for (int kk = 0; kk < 2; kk++) {
            const int kb = kk * 8;
            unsigned a[2][4], b[4][2];
#pragma unroll
            for (int mi = 0; mi < 2; mi++) {
                const int ar = wm + mi * 16;
                a[mi][0] = As[(ar + g) * 20 + kb + t4];
                a[mi][1] = As[(ar + g + 8) * 20 + kb + t4];
                a[mi][2] = As[(ar + g) * 20 + kb + t4 + 4];
                a[mi][3] = As[(ar + g + 8) * 20 + kb + t4 + 4];
            }
#pragma unroll
            for (int ni = 0; ni < 4; ni++) {
                const int bc = wn + ni * 8;
                b[ni][0] = Bs[(bc + g) * 20 + kb + t4];
                b[ni][1] = Bs[(bc + g) * 20 + kb + t4 + 4];
            }
#pragma unroll
            for (int mi = 0; mi < 2; mi++)
#pragma unroll
                for (int ni = 0; ni < 4; ni++)
                    mma_tf32(acc[mi][ni], a[mi], b[ni]);
        }
    }

    const size_t rbase = ((size_t)d * kS + s) * kB;
#pragma unroll
    for (int ni = 0; ni < 4; ni++) {
        const int col = n0 + wn + ni * 8 + t4 * 2;
        const float bs0 = bi[col] + bh[col];
        const float bs1 = bi[col + 1] + bh[col + 1];
#pragma unroll
        for (int mi = 0; mi < 2; mi++) {
            const int r0 = wm + mi * 16 + g;
            float2 v;
            v.x = acc[mi][ni][0] + bs0; v.y = acc[mi][ni][1] + bs1;
            *(float2*)&g_gx[(rbase + r0) * kG + col] = v;
            v.x = acc[mi][ni][2] + bs0; v.y = acc[mi][ni][3] + bs1;
            *(float2*)&g_gx[(rbase + r0 + 8) * kG + col] = v;
        }
    }
}

// ---------------------------------------------------------------------------
// Kernel 2: recurrence on tensor cores. 16 clusters of 8 CTAs, 256 thr/CTA.
// Warp-autonomous compute (R14/R15): warp w owns all 4 gates of units
// 4w..4w+3 as persistent full-M tf32 A-fragments; per step: mma (K=256,
// dual chains) -> 2-round shfl transpose -> gate math -> shfl-pack ->
// 7-peer DSMEM st.v4. CTA-aggregated handshake (R15): one __syncthreads,
// tid<8 send one arrive.release.cluster each (release covers ALL warps'
// stores via the syncthreads HB -- no separate fence needed).
// NEW in R16: the wait loop polls with RELAXED cta-scope try_wait and pays
// the cluster-scope ordering cost ONCE via a post-success
// fence.acq_rel.cluster (release-fence/acquire-fence synchronization
// through the mbarrier word). Per-poll acquire.cluster (~hundreds of cyc,
// the suspected hidden per-step tax) is eliminated.
// Dual phase-alternating mbarriers (count 8), parity (step>>1)&1.
// ---------------------------------------------------------------------------
constexpr int HB_STR = 260;   // h row stride: conflict-free b-frag LDS

__global__ void __launch_bounds__(256, 1) lstm_rec(
    const float* __restrict__ whf, const float* __restrict__ whb,
    const float* __restrict__ h0f, const float* __restrict__ c0f,
    const float* __restrict__ h0b, const float* __restrict__ c0b,
    float* __restrict__ out)
{
    __shared__ alignas(16) float hb[2][8][HB_STR];   // double-buffered h
    __shared__ alignas(8) unsigned long long mbar[2];

    unsigned rank;
    asm("mov.u32 %0, %%cluster_ctarank;" : "=r"(rank));
    unsigned hb_base;
    asm("{ .reg .u64 t; cvta.to.shared.u64 t, %1; cvt.u32.u64 %0, t; }"
        : "=r"(hb_base) : "l"(&hb[0][0][0]));
    unsigned mb_base;
    asm("{ .reg .u64 t; cvta.to.shared.u64 t, %1; cvt.u32.u64 %0, t; }"
        : "=r"(mb_base) : "l"(&mbar[0]));

    const int cid = blockIdx.x >> 3;   // cluster 0..15
    const int dir = cid >> 3;          // 0 fwd, 1 bwd
    const int bg  = cid & 7;
    const int gb0 = bg * 8;
    const int tid = threadIdx.x;
    const int w    = tid >> 5;         // warp 0..7
    const int lane = tid & 31;
    const int g    = lane >> 2;        // fragment group 0..7
    const int t4   = lane & 3;         // thread-in-group
    const int bit2 = (lane >> 2) & 1;
    const int bit3 = (lane >> 3) & 1;
    const int bit4 = (lane >> 4) & 1;

    // Gate-phase ownership: one (unit, batch) per thread
    const int u_idx = 2 * bit3 + bit4;              // 0..3
    const int u     = 4 * w + u_idx;                // CTA-local unit 0..31
    const int gb    = ((lane & 3) << 1) | bit2;     // batch-in-group 0..7

    const float* whh = dir == 0 ? whf : whb;
    const float* h0  = dir == 0 ? h0f : h0b;
    const float* c0  = dir == 0 ? c0f : c0b;

    // mbarriers: 8 arrivals per phase (one per cluster CTA)
    if (tid == 0) {
        asm volatile("mbarrier.init.shared.b64 [%0], %1;" :: "r"(mb_base), "r"(8u) : "memory");
        asm volatile("mbarrier.init.shared.b64 [%0], %1;" :: "r"(mb_base + 8), "r"(8u) : "memory");
    }

    // Persistent FULL-M A-fragments: rows r_lo = 16w+g, r_hi = r_lo+8
    const int r_lo = 16 * w + g;
    const int r_hi = r_lo + 8;
    const int wr_lo = (r_lo & 3) * 256 + (int)rank * 32 + (r_lo >> 2);
    const int wr_hi = (r_hi & 3) * 256 + (int)rank * 32 + (r_hi >> 2);
    unsigned a0[32], a1[32], a2[32], a3[32];
#pragma unroll
    for (int kc = 0; kc < 32; kc++) {
        a0[kc] = f2tf(whh[(size_t)wr_lo * kH + kc * 8 + t4]);
        a1[kc] = f2tf(whh[(size_t)wr_hi * kH + kc * 8 + t4]);
        a2[kc] = f2tf(whh[(size_t)wr_lo * kH + kc * 8 + t4 + 4]);
        a3[kc] = f2tf(whh[(size_t)wr_hi * kH + kc * 8 + t4 + 4]);
    }

    // Load h0 into buffer 0 (tf32-rounded, consistent with mainloop h)
    for (int idx = tid; idx < 8 * 64; idx += 256) {
        const int b = idx >> 6, k4 = (idx & 63) * 4;
        float4 v = *(const float4*)(h0 + (size_t)(gb0 + b) * kH + k4);
        float4 o4;
        o4.x = __uint_as_float(f2tf(v.x)); o4.y = __uint_as_float(f2tf(v.y));
        o4.z = __uint_as_float(f2tf(v.z)); o4.w = __uint_as_float(f2tf(v.w));
        *(float4*)&hb[0][b][k4] = o4;
    }

    float cst = c0[(size_t)(gb0 + gb) * kH + (int)rank * 32 + u];
    const size_t gx_addr0 = ((size_t)dir * kS * kB + (gb0 + gb)) * kG
                            + (size_t)rank * 32 + u;

    __syncthreads();
    // One-time cluster barrier: peers' mbarrier init + h0 visible before use
    asm volatile("barrier.cluster.arrive.aligned;" ::: "memory");
    asm volatile("barrier.cluster.wait.aligned;" ::: "memory");

    // Preload gx for step 0
    float gx0, gx1, gx2, gx3;
    {
        const int t0 = (dir == 0) ? 0 : (kS - 1);
        const size_t a = gx_addr0 + (size_t)t0 * (kB * kG);
        gx0 = g_gx[a]; gx1 = g_gx[a + 256]; gx2 = g_gx[a + 512]; gx3 = g_gx[a + 768];
    }

    int p = 0;
    for (int step = 0; step < kS; step++) {
        const int t = (dir == 0) ? step : (kS - 1 - step);

        // Prefetch NEXT step's gx (hidden under the mma loop)
        float gn0 = 0.f, gn1 = 0.f, gn2 = 0.f, gn3 = 0.f;
        if (step + 1 < kS) {
            const int tn = (dir == 0) ? (step + 1) : (kS - 2 - step);
            const size_t a = gx_addr0 + (size_t)tn * (kB * kG);
            gn0 = g_gx[a]; gn1 = g_gx[a + 256]; gn2 = g_gx[a + 512]; gn3 = g_gx[a + 768];
        }

        // Tensor mainloop over K=256: two independent accumulation chains
        float cE[4] = {0.f, 0.f, 0.f, 0.f};
        float cO[4] = {0.f, 0.f, 0.f, 0.f};
        const float* hcur = &hb[p][0][0];
        const int hoff = g * HB_STR + t4;
#pragma unroll
        for (int kc = 0; kc < 32; kc += 2) {
            {
                const unsigned b0 = __float_as_uint(hcur[hoff + kc * 8]);
                const unsigned b1 = __float_as_uint(hcur[hoff + kc * 8 + 4]);
                const unsigned af[4] = {a0[kc], a1[kc], a2[kc], a3[kc]};
                const unsigned bf[2] = {b0, b1};
                mma_tf32(cE, af, bf);
            }
            {
                const unsigned b0 = __float_as_uint(hcur[hoff + (kc + 1) * 8]);
                const unsigned b1 = __float_as_uint(hcur[hoff + (kc + 1) * 8 + 4]);
                const unsigned af[4] = {a0[kc + 1], a1[kc + 1], a2[kc + 1], a3[kc + 1]};
                const unsigned bf[2] = {b0, b1};
                mma_tf32(cO, af, bf);
            }
        }

        // Thread (g,t4) holds: v0=(row r_lo, b=2t4), v1=(r_lo, 2t4+1),
        //                      v2=(r_hi, 2t4),     v3=(r_hi, 2t4+1)
        const float v0 = cE[0] + cO[0];
        const float v1 = cE[1] + cO[1];
        const float v2 = cE[2] + cO[2];
        const float v3 = cE[3] + cO[3];

        // Round 1 (xor 4): keep batch-parity == bit2, trade for gate-bit0
        const float keepA = bit2 ? v1 : v0;
        const float sendA = bit2 ? v0 : v1;
        const float keepB = bit2 ? v3 : v2;
        const float sendB = bit2 ? v2 : v3;
        const float gotA = __shfl_xor_sync(0xffffffffu, sendA, 4);
        const float gotB = __shfl_xor_sync(0xffffffffu, sendB, 4);
        const float a_g0 = bit2 ? gotA : keepA;   // (u_hi=0, gate bit0 = 0)
        const float a_g1 = bit2 ? keepA : gotA;   // (u_hi=0, gate bit0 = 1)
        const float b_g0 = bit2 ? gotB : keepB;   // (u_hi=1, gate bit0 = 0)
        const float b_g1 = bit2 ? keepB : gotB;

        // Round 2 (xor 8): keep unit_hi == bit3, trade for gate-bit1
        const float keepX = bit3 ? b_g0 : a_g0;
        const float sendX = bit3 ? a_g0 : b_g0;
        const float keepY = bit3 ? b_g1 : a_g1;
        const float sendY = bit3 ? a_g1 : b_g1;
        const float gotX = __shfl_xor_sync(0xffffffffu, sendX, 8);
        const float gotY = __shfl_xor_sync(0xffffffffu, sendY, 8);
        const float pi = bit3 ? gotX : keepX;   // gate 0 (i)
        const float pf = bit3 ? gotY : keepY;   // gate 1 (f)
        const float pg = bit3 ? keepX : gotX;   // gate 2 (g)
        const float po = bit3 ? keepY : gotY;   // gate 3 (o)

        // Gate math for (unit u, batch gb)
        const float gi = pi + gx0;
        const float gf = pf + gx1;
        const float gg = pg + gx2;
        const float go = po + gx3;
        cst = sigf(gf) * cst + sigf(gi) * tanhf_(gg);
        const float hnew = sigf(go) * tanhf_(cst);
        const float hr = __uint_as_float(f2tf(hnew));   // rounded for recurrence

        hb[p ^ 1][gb][(int)rank * 32 + u] = hr;
        out[(((size_t)(gb0 + gb)) * kS + t) * 512
            + dir * kH + (int)rank * 32 + u] = hnew;

        if (step + 1 < kS) {
            // Pack units 4w..4w+3 of this thread's batch into a float4.
            // Lanes 0..7 (bits3,4 = 0) end holding their batch's full pack.
            const float p1 = __shfl_xor_sync(0xffffffffu, hr, 16);  // u_idx 1
            const float p2 = __shfl_xor_sync(0xffffffffu, hr, 8);   // u_idx 2
            const float p3 = __shfl_xor_sync(0xffffffffu, hr, 24);  // u_idx 3
            if (lane < 8) {
                const unsigned loff = hb_base +
                    (unsigned)((((p ^ 1) * 8 + gb) * HB_STR)
                               + (int)rank * 32 + 4 * w) * 4u;
#pragma unroll
                for (int j = 0; j < 7; j++) {
                    const unsigned tr = (rank + 1u + (unsigned)((lane + j) % 7)) & 7u;
                    unsigned raddr;
                    asm("mapa.shared::cluster.u32 %0, %1, %2;"
                        : "=r"(raddr) : "r"(loff), "r"(tr));
                    asm volatile("st.shared::cluster.v4.f32 [%0], {%1,%2,%3,%4};"
                                 :: "r"(raddr), "f"(hr), "f"(p1), "f"(p2), "f"(p3));
                }
            }

            // CTA-aggregated handshake: syncthreads orders ALL warps' remote
            // stores before the release-arrives (release covers them via HB).
            __syncthreads();
            const unsigned mb_q = mb_base + (unsigned)((step & 1) * 8);
            if (tid < 8) {
                unsigned raddr;
                asm("mapa.shared::cluster.u32 %0, %1, %2;"
                    : "=r"(raddr) : "r"(mb_q), "r"((unsigned)tid));
                asm volatile("mbarrier.arrive.release.cluster.shared::cluster.b64 _, [%0];"
                             :: "r"(raddr) : "memory");
            }
            // Wait: RELAXED polls (cta scope, cheap), then ONE cluster-scope
            // acquire fence after the observed flip (fence-fence sync with
            // the peers' release-arrives).
            const unsigned par = (unsigned)((step >> 1) & 1);
            unsigned done = 0;
            while (!done) {
                asm volatile(
                    "{\n\t.reg .pred p;\n\t"
                    "mbarrier.try_wait.parity.relaxed.cta.shared::cta.b64 p, [%1], %2, 0x989680;\n\t"
                    "selp.b32 %0, 1, 0, p;\n\t}"
                    : "=r"(done) : "r"(mb_q), "r"(par) : "memory");
            }
            asm volatile("fence.acq_rel.cluster;" ::: "memory");
        }

        gx0 = gn0; gx1 = gn1; gx2 = gn2; gx3 = gn3;
        p ^= 1;
    }

    // Keep SMEM alive until all peers are past their last remote stores
    asm volatile("barrier.cluster.arrive.aligned;" ::: "memory");
    asm volatile("barrier.cluster.wait.aligned;" ::: "memory");
}

// ---------------------------------------------------------------------------
// Launch
// ---------------------------------------------------------------------------
extern "C" void kernel_launch(void* const* d_in, const int* in_sizes, int n_in,
                              void* d_out, int out_size)
{
    const float* X   = (const float*)d_in[0];
    const float* Wf  = (const float*)d_in[1];
    const float* Whf = (const float*)d_in[2];
    const float* bif = (const float*)d_in[3];
    const float* bhf = (const float*)d_in[4];
    const float* Wb  = (const float*)d_in[5];
    const float* Whb = (const float*)d_in[6];
    const float* bib = (const float*)d_in[7];
    const float* bhb = (const float*)d_in[8];
    const float* h0f = (const float*)d_in[9];
    const float* c0f = (const float*)d_in[10];
    const float* h0b = (const float*)d_in[11];
    const float* c0b = (const float*)d_in[12];
    float* out = (float*)d_out;

    dim3 g1(16, 2048, 2);
    gemm_in<<<g1, 128>>>(X, Wf, bif, bhf, Wb, bib, bhb);

    cudaLaunchConfig_t cfg = {};
    cfg.gridDim = dim3(128, 1, 1);
    cfg.blockDim = dim3(256, 1, 1);
    cfg.dynamicSmemBytes = 0;
    cfg.stream = 0;
    cudaLaunchAttribute attr[1];
    attr[0].id = cudaLaunchAttributeClusterDimension;
    attr[0].val.clusterDim.x = 8;
    attr[0].val.clusterDim.y = 1;
    attr[0].val.clusterDim.z = 1;
    cfg.attrs = attr;
    cfg.numAttrs = 1;
    cudaLaunchKernelEx(&cfg, lstm_rec, Whf, Whb, h0f, c0f, h0b, c0b, out);
}